// round 7
// baseline (speedup 1.0000x reference)
#include <cuda_runtime.h>
#include <cuda_bf16.h>
#include <math.h>

#define GG 128
#define NN 512
#define NV (GG*NN)          // 65536 nodes
#define HH 128              // hidden/feature dim
#define EE 2097152          // directed edges (2 * G * E_HALF)
#define EHALF 8192
#define EPG 16384           // directed edges per graph
#define LL 5
#define CC 10

// Scratch (device globals: allocation-free per harness rules)
__device__ float    g_bufA[NV * HH];        // 32 MB
__device__ float    g_bufB[NV * HH];        // 32 MB
__device__ int      g_row_ptr[NV + 1];
__device__ int      g_edge_off[EE];         // 8 MB: local src index * 32 (float4 row offset)
__device__ unsigned g_Wth[LL * HH * 64];    // W^T hi, packed bf16 k-pairs [l][n][kw]
__device__ unsigned g_Wtl[LL * HH * 64];    // W^T lo
__device__ float    g_part[GG * 8 * HH];    // readout partials

// ---------------------------------------------------------------- fused CSR build
__global__ void __launch_bounds__(512) k_csr(const int* __restrict__ src,
                                             const int* __restrict__ dst) {
    __shared__ int cnt[NN];
    __shared__ int pos[NN];
    int g = blockIdx.x, t = threadIdx.x;
    cnt[t] = 0;
    __syncthreads();

    int base1 = g * EHALF;
    int base2 = GG * EHALF + g * EHALF;
    for (int i = t; i < EHALF; i += 512) {
        atomicAdd(&cnt[dst[base1 + i] & (NN - 1)], 1);
        atomicAdd(&cnt[dst[base2 + i] & (NN - 1)], 1);
    }
    __syncthreads();

    int c = cnt[t];
    pos[t] = c;
    __syncthreads();
    for (int off = 1; off < NN; off <<= 1) {
        int v = (t >= off) ? pos[t - off] : 0;
        __syncthreads();
        pos[t] += v;
        __syncthreads();
    }
    int startLocal = pos[t] - c;
    g_row_ptr[g * NN + t] = g * EPG + startLocal;
    cnt[t] = startLocal;
    if (g == 0 && t == 0) g_row_ptr[NV] = EE;
    __syncthreads();

    int* eout = g_edge_off + g * EPG;
    for (int i = t; i < EHALF; i += 512) {
        int d = dst[base1 + i] & (NN - 1);
        int p = atomicAdd(&cnt[d], 1);
        eout[p] = (src[base1 + i] & (NN - 1)) * 32;
        d = dst[base2 + i] & (NN - 1);
        p = atomicAdd(&cnt[d], 1);
        eout[p] = (src[base2 + i] & (NN - 1)) * 32;
    }
}

// ---------------------------------------------------------------- W prep: transpose + bf16 hi/lo split
__global__ void k_prepw(const float* __restrict__ W) {
    int i = blockIdx.x * blockDim.x + threadIdx.x;
    if (i >= LL * HH * 64) return;
    int kw = i & 63;
    int n  = (i >> 6) & (HH - 1);
    int l  = i >> 13;
    const float* Wl = W + l * HH * HH;
    float w0 = Wl[(2 * kw) * HH + n];
    float w1 = Wl[(2 * kw + 1) * HH + n];
    __nv_bfloat162 h = __float22bfloat162_rn(make_float2(w0, w1));
    float2 hf = __bfloat1622float2(h);
    __nv_bfloat162 lo = __float22bfloat162_rn(make_float2(w0 - hf.x, w1 - hf.y));
    g_Wth[i] = *reinterpret_cast<unsigned*>(&h);
    g_Wtl[i] = *reinterpret_cast<unsigned*>(&lo);
}

// ---------------------------------------------------------------- SpMM + combine
// One warp per node: lane owns one float4. Unroll 8, dual accumulators (MLP 8).
__global__ void __launch_bounds__(256) k_spmm(const float* __restrict__ xin,
                                              const float* __restrict__ eps,
                                              int layer, int ssel, int dsel) {
    const float* hin  = (ssel == 0) ? xin : (ssel == 1 ? g_bufA : g_bufB);
    float*       uout = (dsel == 1) ? g_bufA : g_bufB;

    int wid  = (blockIdx.x * blockDim.x + threadIdx.x) >> 5;
    int lane = threadIdx.x & 31;

    int g = wid >> 9;                                   // graph id
    const float4* hg4 = (const float4*)hin + (size_t)g * NN * 32;

    float e1 = 1.0f + __ldg(&eps[layer]);
    int base = wid * 32 + lane;

    int e    = g_row_ptr[wid];
    int eend = g_row_ptr[wid + 1];

    float4 h0 = ((const float4*)hin)[base];
    float4 acc0, acc1;
    acc0.x = e1 * h0.x; acc0.y = e1 * h0.y; acc0.z = e1 * h0.z; acc0.w = e1 * h0.w;
    acc1.x = 0.f; acc1.y = 0.f; acc1.z = 0.f; acc1.w = 0.f;

    for (; e + 8 <= eend; e += 8) {
        int o0 = g_edge_off[e + 0];
        int o1 = g_edge_off[e + 1];
        int o2 = g_edge_off[e + 2];
        int o3 = g_edge_off[e + 3];
        int o4 = g_edge_off[e + 4];
        int o5 = g_edge_off[e + 5];
        int o6 = g_edge_off[e + 6];
        int o7 = g_edge_off[e + 7];
        float4 f0 = hg4[o0 + lane];
        float4 f1 = hg4[o1 + lane];
        float4 f2 = hg4[o2 + lane];
        float4 f3 = hg4[o3 + lane];
        float4 f4 = hg4[o4 + lane];
        float4 f5 = hg4[o5 + lane];
        float4 f6 = hg4[o6 + lane];
        float4 f7 = hg4[o7 + lane];
        acc0.x += f0.x; acc0.y += f0.y; acc0.z += f0.z; acc0.w += f0.w;
        acc1.x += f1.x; acc1.y += f1.y; acc1.z += f1.z; acc1.w += f1.w;
        acc0.x += f2.x; acc0.y += f2.y; acc0.z += f2.z; acc0.w += f2.w;
        acc1.x += f3.x; acc1.y += f3.y; acc1.z += f3.z; acc1.w += f3.w;
        acc0.x += f4.x; acc0.y += f4.y; acc0.z += f4.z; acc0.w += f4.w;
        acc1.x += f5.x; acc1.y += f5.y; acc1.z += f5.z; acc1.w += f5.w;
        acc0.x += f6.x; acc0.y += f6.y; acc0.z += f6.z; acc0.w += f6.w;
        acc1.x += f7.x; acc1.y += f7.y; acc1.z += f7.z; acc1.w += f7.w;
    }
    for (; e < eend; e++) {
        float4 f0 = hg4[g_edge_off[e] + lane];
        acc0.x += f0.x; acc0.y += f0.y; acc0.z += f0.z; acc0.w += f0.w;
    }
    acc0.x += acc1.x; acc0.y += acc1.y; acc0.z += acc1.z; acc0.w += acc1.w;
    ((float4*)uout)[base] = acc0;
}

// ---------------------------------------------------------------- tensor-core GEMM + bias + relu
// h = relu(U @ W_l + b_l), in place. 3-pass bf16 split, fp32 accum.
// A (U): staged to smem bf16 hi/lo planes, read via ldmatrix.x4.
// B (W): direct scalar __ldg from hot global g_Wth/g_Wtl table (L1-resident).

#define SW 136   // bf16 elems per smem row (272 B stride, ldmatrix conflict-free)
#define SMEM_GEMM (2*64*SW*2 + HH*4)

#define MMA_BF16(C, A0, A1, A2, A3, B0, B1)                                      \
    asm volatile("mma.sync.aligned.m16n8k16.row.col.f32.bf16.bf16.f32 "          \
                 "{%0,%1,%2,%3}, {%4,%5,%6,%7}, {%8,%9}, {%0,%1,%2,%3};"         \
                 : "+f"(C[0]), "+f"(C[1]), "+f"(C[2]), "+f"(C[3])                \
                 : "r"(A0), "r"(A1), "r"(A2), "r"(A3), "r"(B0), "r"(B1))

#define LDMX4(R, addr)                                                           \
    asm volatile("ldmatrix.sync.aligned.m8n8.x4.shared.b16 {%0,%1,%2,%3}, [%4];" \
                 : "=r"(R[0]), "=r"(R[1]), "=r"(R[2]), "=r"(R[3]) : "r"(addr))

__global__ void __launch_bounds__(256, 3) k_gemm_tc(const float* __restrict__ b,
                                                    int layer, int bufsel) {
    float* u = (bufsel == 1) ? g_bufA : g_bufB;

    extern __shared__ char smem[];
    __nv_bfloat16* sUh = (__nv_bfloat16*)smem;
    __nv_bfloat16* sUl = sUh + 64 * SW;
    float*         sB  = (float*)(sUl + 64 * SW);

    int tid = threadIdx.x;
    int rowBase = blockIdx.x * 64;

    // ---- stage U (fp32 -> bf16 hi/lo planes) ----
    {
        const float4* u4 = (const float4*)(u + (size_t)rowBase * HH);
#pragma unroll
        for (int k = 0; k < 8; k++) {
            int q = tid + k * 256;            // 2048 float4
            int r = q >> 5, c = (q & 31) * 4;
            float4 v = u4[q];
            __nv_bfloat162 h01 = __float22bfloat162_rn(make_float2(v.x, v.y));
            __nv_bfloat162 h23 = __float22bfloat162_rn(make_float2(v.z, v.w));
            float2 f01 = __bfloat1622float2(h01);
            float2 f23 = __bfloat1622float2(h23);
            __nv_bfloat162 l01 = __float22bfloat162_rn(make_float2(v.x - f01.x, v.y - f01.y));
            __nv_bfloat162 l23 = __float22bfloat162_rn(make_float2(v.z - f23.x, v.w - f23.y));
            uint2 hw, lw;
            hw.x = *(unsigned*)&h01; hw.y = *(unsigned*)&h23;
            lw.x = *(unsigned*)&l01; lw.y = *(unsigned*)&l23;
            *(uint2*)(sUh + r * SW + c) = hw;
            *(uint2*)(sUl + r * SW + c) = lw;
        }
    }
    if (tid < HH) sB[tid] = b[layer * HH + tid];
    __syncthreads();

    int warp = tid >> 5, lane = tid & 31;
    int wm = warp & 1, wn = warp >> 1;
    int rw = wm * 32, nw = wn * 32;

    float acc[2][4][4];
#pragma unroll
    for (int mt = 0; mt < 2; mt++)
#pragma unroll
        for (int j = 0; j < 4; j++)
#pragma unroll
            for (int q = 0; q < 4; q++) acc[mt][j][q] = 0.f;

    // A ldmatrix lane addressing
    int lb = lane >> 3, lr = lane & 7;
    int a_row = (lb & 1) * 8 + lr;
    int a_k   = (lb >> 1) * 8;

    unsigned aH[2], aL[2];
#pragma unroll
    for (int mt = 0; mt < 2; mt++) {
        int row = rw + mt * 16 + a_row;
        aH[mt] = (unsigned)__cvta_generic_to_shared(sUh + row * SW + a_k);
        aL[mt] = (unsigned)__cvta_generic_to_shared(sUl + row * SW + a_k);
    }

    // B scalar-fragment addressing (R3 convention): thread (g2, tg)
    int g2 = lane >> 2, tg = lane & 3;
    const unsigned* WhL = g_Wth + layer * HH * 64;
    const unsigned* WlL = g_Wtl + layer * HH * 64;

#pragma unroll
    for (int ks = 0; ks < 8; ks++) {
        unsigned ko = (unsigned)ks * 32;      // 16 bf16 = 32 bytes
        unsigned Ah[2][4], Al[2][4];
        LDMX4(Ah[0], aH[0] + ko); LDMX4(Ah[1], aH[1] + ko);
        LDMX4(Al[0], aL[0] + ko); LDMX4(Al[1], aL[1] + ko);
        int kp = ks * 8 + tg;
#pragma unroll
        for (int j = 0; j < 4; j++) {
            const unsigned* wh = WhL + (nw + j * 8 + g2) * 64 + kp;
            const unsigned* wl = WlL + (nw + j * 8 + g2) * 64 + kp;
            unsigned bh0 = __ldg(wh), bh1 = __ldg(wh + 4);
            unsigned bl0 = __ldg(wl), bl1 = __ldg(wl + 4);
#pragma unroll
            for (int mt = 0; mt < 2; mt++) {
                MMA_BF16(acc[mt][j], Ah[mt][0], Ah[mt][1], Ah[mt][2], Ah[mt][3], bh0, bh1);
                MMA_BF16(acc[mt][j], Al[mt][0], Al[mt][1], Al[mt][2], Al[mt][3], bh0, bh1);
                MMA_BF16(acc[mt][j], Ah[mt][0], Ah[mt][1], Ah[mt][2], Ah[mt][3], bl0, bl1);
            }
        }
    }

    // ---- epilogue: bias + relu, store fp32 in place ----
#pragma unroll
    for (int mt = 0; mt < 2; mt++) {
        int rA = rowBase + rw + mt * 16 + g2;
        int rB = rA + 8;
#pragma unroll
        for (int j = 0; j < 4; j++) {
            int c = nw + j * 8 + 2 * tg;
            float b0 = sB[c], b1 = sB[c + 1];
            float2 oA, oB;
            oA.x = fmaxf(acc[mt][j][0] + b0, 0.f);
            oA.y = fmaxf(acc[mt][j][1] + b1, 0.f);
            oB.x = fmaxf(acc[mt][j][2] + b0, 0.f);
            oB.y = fmaxf(acc[mt][j][3] + b1, 0.f);
            *(float2*)(u + (size_t)rA * HH + c) = oA;
            *(float2*)(u + (size_t)rB * HH + c) = oB;
        }
    }
}

// ---------------------------------------------------------------- readout stage 1: partial node sums
// 8 CTAs per graph, each sums 64 rows; thread = one feature.
__global__ void __launch_bounds__(128) k_sum(int bufsel) {
    const float* h = (bufsel == 1) ? g_bufA : g_bufB;
    int g = blockIdx.x >> 3, p = blockIdx.x & 7;
    int t = threadIdx.x;
    const float* base = h + (size_t)g * NN * HH + p * 64 * HH + t;
    float s0 = 0.f, s1 = 0.f;
#pragma unroll 8
    for (int r = 0; r < 64; r += 2) {
        s0 += base[r * HH];
        s1 += base[(r + 1) * HH];
    }
    g_part[(g * 8 + p) * HH + t] = s0 + s1;
}

// ---------------------------------------------------------------- readout stage 2: FCs + softmax
__global__ void __launch_bounds__(128) k_fc(const float* __restrict__ fc1w,
                                            const float* __restrict__ fc1b,
                                            const float* __restrict__ fc2w,
                                            const float* __restrict__ fc2b,
                                            float* __restrict__ out) {
    __shared__ float hg[HH];
    __shared__ float a1[HH];
    __shared__ float z[CC];
    __shared__ float ez[CC];

    int g = blockIdx.x;
    int t = threadIdx.x;

    float s = 0.f;
#pragma unroll
    for (int p = 0; p < 8; p++) s += g_part[(g * 8 + p) * HH + t];
    hg[t] = s;
    __syncthreads();

    {
        float acc = fc1b[t];
        for (int k = 0; k < HH; k++) acc += hg[k] * __ldg(&fc1w[k * HH + t]);
        a1[t] = fmaxf(acc, 0.f);
    }
    __syncthreads();

    if (t < CC) {
        float acc = fc2b[t];
        for (int k = 0; k < HH; k++) acc += a1[k] * __ldg(&fc2w[k * CC + t]);
        z[t] = acc;
    }
    __syncthreads();

    if (t < CC) {
        float m = z[0];
#pragma unroll
        for (int j = 1; j < CC; j++) m = fmaxf(m, z[j]);
        ez[t] = expf(z[t] - m);
    }
    __syncthreads();

    if (t < CC) {
        float ssum = 0.f;
#pragma unroll
        for (int j = 0; j < CC; j++) ssum += ez[j];
        out[g * CC + t] = ez[t] / ssum;
    }
}

// ---------------------------------------------------------------- launch
extern "C" void kernel_launch(void* const* d_in, const int* in_sizes, int n_in,
                              void* d_out, int out_size) {
    const float* x    = (const float*)d_in[0];
    const float* eps  = (const float*)d_in[1];
    const float* W    = (const float*)d_in[2];
    const float* b    = (const float*)d_in[3];
    const float* fc1w = (const float*)d_in[4];
    const float* fc1b = (const float*)d_in[5];
    const float* fc2w = (const float*)d_in[6];
    const float* fc2b = (const float*)d_in[7];
    const int*   src  = (const int*)d_in[8];
    const int*   dst  = (const int*)d_in[9];
    float* out = (float*)d_out;

    cudaFuncSetAttribute(k_gemm_tc, cudaFuncAttributeMaxDynamicSharedMemorySize,
                         SMEM_GEMM);

    k_csr<<<GG, 512>>>(src, dst);
    k_prepw<<<(LL * HH * 64 + 255) / 256, 256>>>(W);

    // 0: x->A, 1: A->B, 2: B->A, 3: A->B, 4: B->A. Final h in A.
    const int ssel[LL] = {0, 1, 2, 1, 2};
    const int dsel[LL] = {1, 2, 1, 2, 1};
    for (int l = 0; l < LL; l++) {
        k_spmm<<<NV / 8, 256>>>(x, eps, l, ssel[l], dsel[l]);
        k_gemm_tc<<<NV / 64, 256, SMEM_GEMM>>>(b, l, dsel[l]);
    }

    k_sum<<<GG * 8, 128>>>(1);
    k_fc<<<GG, 128>>>(fc1w, fc1b, fc2w, fc2b, out);
}

// round 8
// speedup vs baseline: 1.2353x; 1.2353x over previous
#include <cuda_runtime.h>
#include <cuda_bf16.h>
#include <math.h>

#define GG 128
#define NN 512
#define NV (GG*NN)          // 65536 nodes
#define HH 128              // hidden/feature dim
#define EE 2097152          // directed edges (2 * G * E_HALF)
#define EHALF 8192
#define EPG 16384           // directed edges per graph
#define LL 5
#define CC 10

// Scratch (device globals: allocation-free per harness rules)
__device__ float    g_bufA[NV * HH];        // 32 MB
__device__ float    g_bufB[NV * HH];        // 32 MB
__device__ int      g_row_ptr[NV + 1];
__device__ int      g_edge_off[EE];         // 8 MB: local src index * 32 (float4 row offset)
__device__ unsigned g_Wth[LL * HH * 64];    // W^T hi, packed bf16 k-pairs [l][n][kw]
__device__ unsigned g_Wtl[LL * HH * 64];    // W^T lo
__device__ float    g_part[GG * 8 * HH];    // readout partials

// ---------------------------------------------------------------- fused CSR build
__global__ void __launch_bounds__(512) k_csr(const int* __restrict__ src,
                                             const int* __restrict__ dst) {
    __shared__ int cnt[NN];
    __shared__ int pos[NN];
    int g = blockIdx.x, t = threadIdx.x;
    cnt[t] = 0;
    __syncthreads();

    int base1 = g * EHALF;
    int base2 = GG * EHALF + g * EHALF;
    for (int i = t; i < EHALF; i += 512) {
        atomicAdd(&cnt[dst[base1 + i] & (NN - 1)], 1);
        atomicAdd(&cnt[dst[base2 + i] & (NN - 1)], 1);
    }
    __syncthreads();

    int c = cnt[t];
    pos[t] = c;
    __syncthreads();
    for (int off = 1; off < NN; off <<= 1) {
        int v = (t >= off) ? pos[t - off] : 0;
        __syncthreads();
        pos[t] += v;
        __syncthreads();
    }
    int startLocal = pos[t] - c;
    g_row_ptr[g * NN + t] = g * EPG + startLocal;
    cnt[t] = startLocal;
    if (g == 0 && t == 0) g_row_ptr[NV] = EE;
    __syncthreads();

    int* eout = g_edge_off + g * EPG;
    for (int i = t; i < EHALF; i += 512) {
        int d = dst[base1 + i] & (NN - 1);
        int p = atomicAdd(&cnt[d], 1);
        eout[p] = (src[base1 + i] & (NN - 1)) * 32;
        d = dst[base2 + i] & (NN - 1);
        p = atomicAdd(&cnt[d], 1);
        eout[p] = (src[base2 + i] & (NN - 1)) * 32;
    }
}

// ---------------------------------------------------------------- W prep: transpose + bf16 hi/lo split
__global__ void k_prepw(const float* __restrict__ W) {
    int i = blockIdx.x * blockDim.x + threadIdx.x;
    if (i >= LL * HH * 64) return;
    int kw = i & 63;
    int n  = (i >> 6) & (HH - 1);
    int l  = i >> 13;
    const float* Wl = W + l * HH * HH;
    float w0 = Wl[(2 * kw) * HH + n];
    float w1 = Wl[(2 * kw + 1) * HH + n];
    __nv_bfloat162 h = __float22bfloat162_rn(make_float2(w0, w1));
    float2 hf = __bfloat1622float2(h);
    __nv_bfloat162 lo = __float22bfloat162_rn(make_float2(w0 - hf.x, w1 - hf.y));
    g_Wth[i] = *reinterpret_cast<unsigned*>(&h);
    g_Wtl[i] = *reinterpret_cast<unsigned*>(&lo);
}

// ---------------------------------------------------------------- SpMM + combine (R3 structure, unroll 4)
// One warp per node: lane owns one float4 (4 of 128 feats).
__global__ void __launch_bounds__(256) k_spmm(const float* __restrict__ xin,
                                              const float* __restrict__ eps,
                                              int layer, int ssel, int dsel) {
    const float* hin  = (ssel == 0) ? xin : (ssel == 1 ? g_bufA : g_bufB);
    float*       uout = (dsel == 1) ? g_bufA : g_bufB;

    int wid  = (blockIdx.x * blockDim.x + threadIdx.x) >> 5;
    int lane = threadIdx.x & 31;

    int g = wid >> 9;                                   // graph id
    const float4* hg4 = (const float4*)hin + (size_t)g * NN * 32;

    float e1 = 1.0f + __ldg(&eps[layer]);
    int base = wid * 32 + lane;

    float4 h0 = ((const float4*)hin)[base];
    float4 acc;
    acc.x = e1 * h0.x; acc.y = e1 * h0.y; acc.z = e1 * h0.z; acc.w = e1 * h0.w;

    int e    = g_row_ptr[wid];
    int eend = g_row_ptr[wid + 1];

    for (; e + 4 <= eend; e += 4) {
        int o0 = g_edge_off[e + 0];
        int o1 = g_edge_off[e + 1];
        int o2 = g_edge_off[e + 2];
        int o3 = g_edge_off[e + 3];
        float4 f0 = hg4[o0 + lane];
        float4 f1 = hg4[o1 + lane];
        float4 f2 = hg4[o2 + lane];
        float4 f3 = hg4[o3 + lane];
        acc.x += f0.x; acc.y += f0.y; acc.z += f0.z; acc.w += f0.w;
        acc.x += f1.x; acc.y += f1.y; acc.z += f1.z; acc.w += f1.w;
        acc.x += f2.x; acc.y += f2.y; acc.z += f2.z; acc.w += f2.w;
        acc.x += f3.x; acc.y += f3.y; acc.z += f3.z; acc.w += f3.w;
    }
    for (; e < eend; e++) {
        float4 f0 = hg4[g_edge_off[e] + lane];
        acc.x += f0.x; acc.y += f0.y; acc.z += f0.z; acc.w += f0.w;
    }
    ((float4*)uout)[base] = acc;
}

// ---------------------------------------------------------------- tensor-core GEMM + bias + relu
// h = relu(U @ W_l + b_l), in place. 3-pass bf16 split, fp32 accum. (R4 kernel,
// extended: each CTA stages W once and processes TWO 64-row U tiles.)
// CTA 256 thr = 8 warps (2 x 4); tile 64 rows x 128 cols; warp 32 x 32.
// All fragments via ldmatrix.x4; U split to bf16 hi/lo at stage time.

#define SW 136   // bf16 elems per smem row (272 B stride, ldmatrix conflict-free)
#define SMEM_GEMM ((64*SW + 64*SW + HH*SW + HH*SW) * 2 + HH * 4)

#define MMA_BF16(C, A0, A1, A2, A3, B0, B1)                                      \
    asm volatile("mma.sync.aligned.m16n8k16.row.col.f32.bf16.bf16.f32 "          \
                 "{%0,%1,%2,%3}, {%4,%5,%6,%7}, {%8,%9}, {%0,%1,%2,%3};"         \
                 : "+f"(C[0]), "+f"(C[1]), "+f"(C[2]), "+f"(C[3])                \
                 : "r"(A0), "r"(A1), "r"(A2), "r"(A3), "r"(B0), "r"(B1))

#define LDMX4(R, addr)                                                           \
    asm volatile("ldmatrix.sync.aligned.m8n8.x4.shared.b16 {%0,%1,%2,%3}, [%4];" \
                 : "=r"(R[0]), "=r"(R[1]), "=r"(R[2]), "=r"(R[3]) : "r"(addr))

__global__ void __launch_bounds__(256) k_gemm_tc(const float* __restrict__ b,
                                                 int layer, int bufsel) {
    float* u = (bufsel == 1) ? g_bufA : g_bufB;

    extern __shared__ char smem[];
    __nv_bfloat16* sUh = (__nv_bfloat16*)smem;
    __nv_bfloat16* sUl = sUh + 64 * SW;
    __nv_bfloat16* sWh = sUl + 64 * SW;
    __nv_bfloat16* sWl = sWh + HH * SW;
    float*         sB  = (float*)(sWl + HH * SW);

    int tid = threadIdx.x;

    // ---- stage W hi/lo once (already packed bf16 [n][k]) ----
    {
        const uint4* wh4 = (const uint4*)(g_Wth + layer * HH * 64);
        const uint4* wl4 = (const uint4*)(g_Wtl + layer * HH * 64);
#pragma unroll
        for (int k = 0; k < 8; k++) {
            int q = tid + k * 256;            // 2048 uint4
            int n = q >> 4, cw = (q & 15) * 4;
            *(uint4*)(sWh + n * SW + cw * 2) = wh4[q];
            *(uint4*)(sWl + n * SW + cw * 2) = wl4[q];
        }
    }
    if (tid < HH) sB[tid] = b[layer * HH + tid];

    int warp = tid >> 5, lane = tid & 31;
    int wm = warp & 1, wn = warp >> 1;
    int rw = wm * 32, nw = wn * 32;

    // ldmatrix lane addressing
    int lb = lane >> 3, lr = lane & 7;
    int a_row = (lb & 1) * 8 + lr;            // blocks: r0k0, r8k0, r0k8, r8k8
    int a_k   = (lb >> 1) * 8;
    int b_n   = (lb >> 1) * 8 + lr;           // blocks: n0k0, n0k8, n8k0, n8k8
    int b_k   = (lb & 1) * 8;

    unsigned aH[2], aL[2], bH[2], bL[2];
#pragma unroll
    for (int mt = 0; mt < 2; mt++) {
        int row = rw + mt * 16 + a_row;
        aH[mt] = (unsigned)__cvta_generic_to_shared(sUh + row * SW + a_k);
        aL[mt] = (unsigned)__cvta_generic_to_shared(sUl + row * SW + a_k);
    }
#pragma unroll
    for (int jp = 0; jp < 2; jp++) {
        int n = nw + jp * 16 + b_n;
        bH[jp] = (unsigned)__cvta_generic_to_shared(sWh + n * SW + b_k);
        bL[jp] = (unsigned)__cvta_generic_to_shared(sWl + n * SW + b_k);
    }

    int g2 = lane >> 2, tg = lane & 3;

#pragma unroll 1
    for (int tile = 0; tile < 2; tile++) {
        int rowBase = blockIdx.x * 128 + tile * 64;

        __syncthreads();   // W ready (tile 0) / previous tile's reads done (tile 1)

        // ---- stage U (fp32 -> bf16 hi/lo planes) ----
        {
            const float4* u4 = (const float4*)(u + (size_t)rowBase * HH);
#pragma unroll
            for (int k = 0; k < 8; k++) {
                int q = tid + k * 256;        // 2048 float4
                int r = q >> 5, c = (q & 31) * 4;
                float4 v = u4[q];
                __nv_bfloat162 h01 = __float22bfloat162_rn(make_float2(v.x, v.y));
                __nv_bfloat162 h23 = __float22bfloat162_rn(make_float2(v.z, v.w));
                float2 f01 = __bfloat1622float2(h01);
                float2 f23 = __bfloat1622float2(h23);
                __nv_bfloat162 l01 = __float22bfloat162_rn(make_float2(v.x - f01.x, v.y - f01.y));
                __nv_bfloat162 l23 = __float22bfloat162_rn(make_float2(v.z - f23.x, v.w - f23.y));
                uint2 hw, lw;
                hw.x = *(unsigned*)&h01; hw.y = *(unsigned*)&h23;
                lw.x = *(unsigned*)&l01; lw.y = *(unsigned*)&l23;
                *(uint2*)(sUh + r * SW + c) = hw;
                *(uint2*)(sUl + r * SW + c) = lw;
            }
        }
        __syncthreads();

        float acc[2][4][4];
#pragma unroll
        for (int mt = 0; mt < 2; mt++)
#pragma unroll
            for (int j = 0; j < 4; j++)
#pragma unroll
                for (int q = 0; q < 4; q++) acc[mt][j][q] = 0.f;

#pragma unroll
        for (int ks = 0; ks < 8; ks++) {
            unsigned ko = (unsigned)ks * 32;  // 16 bf16 = 32 bytes
            unsigned Ah[2][4], Al[2][4];
            LDMX4(Ah[0], aH[0] + ko); LDMX4(Ah[1], aH[1] + ko);
            LDMX4(Al[0], aL[0] + ko); LDMX4(Al[1], aL[1] + ko);
#pragma unroll
            for (int jp = 0; jp < 2; jp++) {
                unsigned Bh[4], Bl[4];
                LDMX4(Bh, bH[jp] + ko);
                LDMX4(Bl, bL[jp] + ko);
#pragma unroll
                for (int mt = 0; mt < 2; mt++) {
#pragma unroll
                    for (int jj = 0; jj < 2; jj++) {
                        int j = jp * 2 + jj;
                        MMA_BF16(acc[mt][j], Ah[mt][0], Ah[mt][1], Ah[mt][2], Ah[mt][3],
                                 Bh[jj * 2], Bh[jj * 2 + 1]);
                        MMA_BF16(acc[mt][j], Al[mt][0], Al[mt][1], Al[mt][2], Al[mt][3],
                                 Bh[jj * 2], Bh[jj * 2 + 1]);
                        MMA_BF16(acc[mt][j], Ah[mt][0], Ah[mt][1], Ah[mt][2], Ah[mt][3],
                                 Bl[jj * 2], Bl[jj * 2 + 1]);
                    }
                }
            }
        }

        // ---- epilogue: bias + relu, store fp32 in place ----
#pragma unroll
        for (int mt = 0; mt < 2; mt++) {
            int rA = rowBase + rw + mt * 16 + g2;
            int rB = rA + 8;
#pragma unroll
            for (int j = 0; j < 4; j++) {
                int c = nw + j * 8 + 2 * tg;
                float b0 = sB[c], b1 = sB[c + 1];
                float2 oA, oB;
                oA.x = fmaxf(acc[mt][j][0] + b0, 0.f);
                oA.y = fmaxf(acc[mt][j][1] + b1, 0.f);
                oB.x = fmaxf(acc[mt][j][2] + b0, 0.f);
                oB.y = fmaxf(acc[mt][j][3] + b1, 0.f);
                *(float2*)(u + (size_t)rA * HH + c) = oA;
                *(float2*)(u + (size_t)rB * HH + c) = oB;
            }
        }
    }
}

// ---------------------------------------------------------------- readout stage 1: partial node sums
__global__ void __launch_bounds__(128) k_sum(int bufsel) {
    const float* h = (bufsel == 1) ? g_bufA : g_bufB;
    int g = blockIdx.x >> 3, p = blockIdx.x & 7;
    int t = threadIdx.x;
    const float* base = h + (size_t)g * NN * HH + p * 64 * HH + t;
    float s0 = 0.f, s1 = 0.f;
#pragma unroll 8
    for (int r = 0; r < 64; r += 2) {
        s0 += base[r * HH];
        s1 += base[(r + 1) * HH];
    }
    g_part[(g * 8 + p) * HH + t] = s0 + s1;
}

// ---------------------------------------------------------------- readout stage 2: FCs + softmax
__global__ void __launch_bounds__(128) k_fc(const float* __restrict__ fc1w,
                                            const float* __restrict__ fc1b,
                                            const float* __restrict__ fc2w,
                                            const float* __restrict__ fc2b,
                                            float* __restrict__ out) {
    __shared__ float hg[HH];
    __shared__ float a1[HH];
    __shared__ float z[CC];
    __shared__ float ez[CC];

    int g = blockIdx.x;
    int t = threadIdx.x;

    float s = 0.f;
#pragma unroll
    for (int p = 0; p < 8; p++) s += g_part[(g * 8 + p) * HH + t];
    hg[t] = s;
    __syncthreads();

    {
        float acc = fc1b[t];
        for (int k = 0; k < HH; k++) acc += hg[k] * __ldg(&fc1w[k * HH + t]);
        a1[t] = fmaxf(acc, 0.f);
    }
    __syncthreads();

    if (t < CC) {
        float acc = fc2b[t];
        for (int k = 0; k < HH; k++) acc += a1[k] * __ldg(&fc2w[k * CC + t]);
        z[t] = acc;
    }
    __syncthreads();

    if (t < CC) {
        float m = z[0];
#pragma unroll
        for (int j = 1; j < CC; j++) m = fmaxf(m, z[j]);
        ez[t] = expf(z[t] - m);
    }
    __syncthreads();

    if (t < CC) {
        float ssum = 0.f;
#pragma unroll
        for (int j = 0; j < CC; j++) ssum += ez[j];
        out[g * CC + t] = ez[t] / ssum;
    }
}

// ---------------------------------------------------------------- launch
extern "C" void kernel_launch(void* const* d_in, const int* in_sizes, int n_in,
                              void* d_out, int out_size) {
    const float* x    = (const float*)d_in[0];
    const float* eps  = (const float*)d_in[1];
    const float* W    = (const float*)d_in[2];
    const float* b    = (const float*)d_in[3];
    const float* fc1w = (const float*)d_in[4];
    const float* fc1b = (const float*)d_in[5];
    const float* fc2w = (const float*)d_in[6];
    const float* fc2b = (const float*)d_in[7];
    const int*   src  = (const int*)d_in[8];
    const int*   dst  = (const int*)d_in[9];
    float* out = (float*)d_out;

    cudaFuncSetAttribute(k_gemm_tc, cudaFuncAttributeMaxDynamicSharedMemorySize,
                         SMEM_GEMM);

    k_csr<<<GG, 512>>>(src, dst);
    k_prepw<<<(LL * HH * 64 + 255) / 256, 256>>>(W);

    // 0: x->A, 1: A->B, 2: B->A, 3: A->B, 4: B->A. Final h in A.
    const int ssel[LL] = {0, 1, 2, 1, 2};
    const int dsel[LL] = {1, 2, 1, 2, 1};
    for (int l = 0; l < LL; l++) {
        k_spmm<<<NV / 8, 256>>>(x, eps, l, ssel[l], dsel[l]);
        k_gemm_tc<<<NV / 128, 256, SMEM_GEMM>>>(b, l, dsel[l]);
    }

    k_sum<<<GG * 8, 128>>>(1);
    k_fc<<<GG, 128>>>(fc1w, fc1b, fc2w, fc2b, out);
}

// round 10
// speedup vs baseline: 1.2602x; 1.0201x over previous
#include <cuda_runtime.h>
#include <cuda_bf16.h>
#include <math.h>

#define GG 128
#define NN 512
#define NV (GG*NN)          // 65536 nodes
#define HH 128              // hidden/feature dim
#define EE 2097152          // directed edges (2 * G * E_HALF)
#define EHALF 8192
#define EPG 16384           // directed edges per graph
#define LL 5
#define CC 10

// Scratch (device globals: allocation-free per harness rules)
__device__ float    g_bufA[NV * HH];        // 32 MB
__device__ float    g_bufB[NV * HH];        // 32 MB
__device__ unsigned g_bufH[NV * 64];        // 16 MB: h as packed bf16x2 (gather copy)
__device__ int      g_row_ptr[NV + 1];
__device__ int      g_edge_off[EE];         // 8 MB: local src index * 32 (row offset in float4/uint2 units)
__device__ unsigned g_Wth[LL * HH * 64];    // W^T hi, packed bf16 k-pairs [l][n][kw]
__device__ unsigned g_Wtl[LL * HH * 64];    // W^T lo
__device__ float    g_part[GG * 8 * HH];    // readout partials

// ---------------------------------------------------------------- fused CSR build
__global__ void __launch_bounds__(512) k_csr(const int* __restrict__ src,
                                             const int* __restrict__ dst) {
    __shared__ int cnt[NN];
    __shared__ int pos[NN];
    int g = blockIdx.x, t = threadIdx.x;
    cnt[t] = 0;
    __syncthreads();

    int base1 = g * EHALF;
    int base2 = GG * EHALF + g * EHALF;
    for (int i = t; i < EHALF; i += 512) {
        atomicAdd(&cnt[dst[base1 + i] & (NN - 1)], 1);
        atomicAdd(&cnt[dst[base2 + i] & (NN - 1)], 1);
    }
    __syncthreads();

    int c = cnt[t];
    pos[t] = c;
    __syncthreads();
    for (int off = 1; off < NN; off <<= 1) {
        int v = (t >= off) ? pos[t - off] : 0;
        __syncthreads();
        pos[t] += v;
        __syncthreads();
    }
    int startLocal = pos[t] - c;
    g_row_ptr[g * NN + t] = g * EPG + startLocal;
    cnt[t] = startLocal;
    if (g == 0 && t == 0) g_row_ptr[NV] = EE;
    __syncthreads();

    int* eout = g_edge_off + g * EPG;
    for (int i = t; i < EHALF; i += 512) {
        int d = dst[base1 + i] & (NN - 1);
        int p = atomicAdd(&cnt[d], 1);
        eout[p] = (src[base1 + i] & (NN - 1)) * 32;
        d = dst[base2 + i] & (NN - 1);
        p = atomicAdd(&cnt[d], 1);
        eout[p] = (src[base2 + i] & (NN - 1)) * 32;
    }
}

// ---------------------------------------------------------------- W prep: transpose + bf16 hi/lo split
__global__ void k_prepw(const float* __restrict__ W) {
    int i = blockIdx.x * blockDim.x + threadIdx.x;
    if (i >= LL * HH * 64) return;
    int kw = i & 63;
    int n  = (i >> 6) & (HH - 1);
    int l  = i >> 13;
    const float* Wl = W + l * HH * HH;
    float w0 = Wl[(2 * kw) * HH + n];
    float w1 = Wl[(2 * kw + 1) * HH + n];
    __nv_bfloat162 h = __float22bfloat162_rn(make_float2(w0, w1));
    float2 hf = __bfloat1622float2(h);
    __nv_bfloat162 lo = __float22bfloat162_rn(make_float2(w0 - hf.x, w1 - hf.y));
    g_Wth[i] = *reinterpret_cast<unsigned*>(&h);
    g_Wtl[i] = *reinterpret_cast<unsigned*>(&lo);
}

// ---------------------------------------------------------------- SpMM layer 1 (fp32 gather, exact)
__global__ void __launch_bounds__(256) k_spmm(const float* __restrict__ xin,
                                              const float* __restrict__ eps) {
    float* uout = g_bufA;
    int wid  = (blockIdx.x * blockDim.x + threadIdx.x) >> 5;
    int lane = threadIdx.x & 31;

    int g = wid >> 9;
    const float4* hg4 = (const float4*)xin + (size_t)g * NN * 32;

    float e1 = 1.0f + __ldg(&eps[0]);
    int base = wid * 32 + lane;

    float4 h0 = ((const float4*)xin)[base];
    float4 acc;
    acc.x = e1 * h0.x; acc.y = e1 * h0.y; acc.z = e1 * h0.z; acc.w = e1 * h0.w;

    int e    = g_row_ptr[wid];
    int eend = g_row_ptr[wid + 1];

    for (; e + 4 <= eend; e += 4) {
        int o0 = g_edge_off[e + 0];
        int o1 = g_edge_off[e + 1];
        int o2 = g_edge_off[e + 2];
        int o3 = g_edge_off[e + 3];
        float4 f0 = hg4[o0 + lane];
        float4 f1 = hg4[o1 + lane];
        float4 f2 = hg4[o2 + lane];
        float4 f3 = hg4[o3 + lane];
        acc.x += f0.x; acc.y += f0.y; acc.z += f0.z; acc.w += f0.w;
        acc.x += f1.x; acc.y += f1.y; acc.z += f1.z; acc.w += f1.w;
        acc.x += f2.x; acc.y += f2.y; acc.z += f2.z; acc.w += f2.w;
        acc.x += f3.x; acc.y += f3.y; acc.z += f3.z; acc.w += f3.w;
    }
    for (; e < eend; e++) {
        float4 f0 = hg4[g_edge_off[e] + lane];
        acc.x += f0.x; acc.y += f0.y; acc.z += f0.z; acc.w += f0.w;
    }
    ((float4*)uout)[base] = acc;
}

// ---------------------------------------------------------------- SpMM layers 2-5 (bf16 gather)
// Neighbor features gathered from packed bf16 copy (g_bufH); self-term and
// accumulation fp32. bf16->fp32 via exact 16-bit shift.
__global__ void __launch_bounds__(256) k_spmm_bf(const float* __restrict__ eps,
                                                 int layer, int ssel, int dsel) {
    const float* hin  = (ssel == 1) ? g_bufA : g_bufB;   // fp32 self-term
    float*       uout = (dsel == 1) ? g_bufA : g_bufB;

    int wid  = (blockIdx.x * blockDim.x + threadIdx.x) >> 5;
    int lane = threadIdx.x & 31;

    int g = wid >> 9;
    const uint2* hg2 = (const uint2*)g_bufH + (size_t)g * NN * 32;

    float e1 = 1.0f + __ldg(&eps[layer]);
    int base = wid * 32 + lane;

    float4 h0 = ((const float4*)hin)[base];
    float4 acc;
    acc.x = e1 * h0.x; acc.y = e1 * h0.y; acc.z = e1 * h0.z; acc.w = e1 * h0.w;
    float4 acc1; acc1.x = 0.f; acc1.y = 0.f; acc1.z = 0.f; acc1.w = 0.f;

    int e    = g_row_ptr[wid];
    int eend = g_row_ptr[wid + 1];

    for (; e + 4 <= eend; e += 4) {
        int o0 = g_edge_off[e + 0];
        int o1 = g_edge_off[e + 1];
        int o2 = g_edge_off[e + 2];
        int o3 = g_edge_off[e + 3];
        uint2 v0 = hg2[o0 + lane];
        uint2 v1 = hg2[o1 + lane];
        uint2 v2 = hg2[o2 + lane];
        uint2 v3 = hg2[o3 + lane];
        acc.x  += __uint_as_float(v0.x << 16);
        acc.y  += __uint_as_float(v0.x & 0xffff0000u);
        acc.z  += __uint_as_float(v0.y << 16);
        acc.w  += __uint_as_float(v0.y & 0xffff0000u);
        acc1.x += __uint_as_float(v1.x << 16);
        acc1.y += __uint_as_float(v1.x & 0xffff0000u);
        acc1.z += __uint_as_float(v1.y << 16);
        acc1.w += __uint_as_float(v1.y & 0xffff0000u);
        acc.x  += __uint_as_float(v2.x << 16);
        acc.y  += __uint_as_float(v2.x & 0xffff0000u);
        acc.z  += __uint_as_float(v2.y << 16);
        acc.w  += __uint_as_float(v2.y & 0xffff0000u);
        acc1.x += __uint_as_float(v3.x << 16);
        acc1.y += __uint_as_float(v3.x & 0xffff0000u);
        acc1.z += __uint_as_float(v3.y << 16);
        acc1.w += __uint_as_float(v3.y & 0xffff0000u);
    }
    for (; e < eend; e++) {
        uint2 v0 = hg2[g_edge_off[e] + lane];
        acc.x += __uint_as_float(v0.x << 16);
        acc.y += __uint_as_float(v0.x & 0xffff0000u);
        acc.z += __uint_as_float(v0.y << 16);
        acc.w += __uint_as_float(v0.y & 0xffff0000u);
    }
    acc.x += acc1.x; acc.y += acc1.y; acc.z += acc1.z; acc.w += acc1.w;
    ((float4*)uout)[base] = acc;
}

// ---------------------------------------------------------------- tensor-core GEMM + bias + relu
// h = relu(U @ W_l + b_l), in place. 3-pass bf16 split, fp32 accum.
// CTA 512 thr = 16 warps (4 x 4); tile 128 rows x 128 cols; warp 32 x 32.
// All fragments via ldmatrix.x4. Epilogue dual-writes fp32 + packed bf16 copy.

#define SW 136   // bf16 elems per smem row (272 B stride, ldmatrix conflict-free)
#define SMEM_GEMM ((128*SW + 128*SW + HH*SW + HH*SW) * 2 + HH * 4)

#define MMA_BF16(C, A0, A1, A2, A3, B0, B1)                                      \
    asm volatile("mma.sync.aligned.m16n8k16.row.col.f32.bf16.bf16.f32 "          \
                 "{%0,%1,%2,%3}, {%4,%5,%6,%7}, {%8,%9}, {%0,%1,%2,%3};"         \
                 : "+f"(C[0]), "+f"(C[1]), "+f"(C[2]), "+f"(C[3])                \
                 : "r"(A0), "r"(A1), "r"(A2), "r"(A3), "r"(B0), "r"(B1))

#define LDMX4(R, addr)                                                           \
    asm volatile("ldmatrix.sync.aligned.m8n8.x4.shared.b16 {%0,%1,%2,%3}, [%4];" \
                 : "=r"(R[0]), "=r"(R[1]), "=r"(R[2]), "=r"(R[3]) : "r"(addr))

__global__ void __launch_bounds__(512) k_gemm_tc(const float* __restrict__ b,
                                                 int layer, int bufsel, int writeBF) {
    float* u = (bufsel == 1) ? g_bufA : g_bufB;

    extern __shared__ char smem[];
    __nv_bfloat16* sUh = (__nv_bfloat16*)smem;
    __nv_bfloat16* sUl = sUh + 128 * SW;
    __nv_bfloat16* sWh = sUl + 128 * SW;
    __nv_bfloat16* sWl = sWh + HH * SW;
    float*         sB  = (float*)(sWl + HH * SW);

    int tid = threadIdx.x;
    int rowBase = blockIdx.x * 128;

    // ---- stage W hi/lo (packed bf16 [n][k]) ----
    {
        const uint4* wh4 = (const uint4*)(g_Wth + layer * HH * 64);
        const uint4* wl4 = (const uint4*)(g_Wtl + layer * HH * 64);
#pragma unroll
        for (int k = 0; k < 4; k++) {
            int q = tid + k * 512;            // 2048 uint4
            int n = q >> 4, cw = (q & 15) * 4;
            *(uint4*)(sWh + n * SW + cw * 2) = wh4[q];
            *(uint4*)(sWl + n * SW + cw * 2) = wl4[q];
        }
    }
    // ---- stage U (fp32 -> bf16 hi/lo planes), 128 rows ----
    {
        const float4* u4 = (const float4*)(u + (size_t)rowBase * HH);
#pragma unroll
        for (int k = 0; k < 8; k++) {
            int q = tid + k * 512;            // 4096 float4
            int r = q >> 5, c = (q & 31) * 4;
            float4 v = u4[q];
            __nv_bfloat162 h01 = __float22bfloat162_rn(make_float2(v.x, v.y));
            __nv_bfloat162 h23 = __float22bfloat162_rn(make_float2(v.z, v.w));
            float2 f01 = __bfloat1622float2(h01);
            float2 f23 = __bfloat1622float2(h23);
            __nv_bfloat162 l01 = __float22bfloat162_rn(make_float2(v.x - f01.x, v.y - f01.y));
            __nv_bfloat162 l23 = __float22bfloat162_rn(make_float2(v.z - f23.x, v.w - f23.y));
            uint2 hw, lw;
            hw.x = *(unsigned*)&h01; hw.y = *(unsigned*)&h23;
            lw.x = *(unsigned*)&l01; lw.y = *(unsigned*)&l23;
            *(uint2*)(sUh + r * SW + c) = hw;
            *(uint2*)(sUl + r * SW + c) = lw;
        }
    }
    if (tid < HH) sB[tid] = b[layer * HH + tid];
    __syncthreads();

    int warp = tid >> 5, lane = tid & 31;
    int wm = warp & 3, wn = warp >> 2;
    int rw = wm * 32, nw = wn * 32;

    float acc[2][4][4];
#pragma unroll
    for (int mt = 0; mt < 2; mt++)
#pragma unroll
        for (int j = 0; j < 4; j++)
#pragma unroll
            for (int q = 0; q < 4; q++) acc[mt][j][q] = 0.f;

    // ldmatrix lane addressing
    int lb = lane >> 3, lr = lane & 7;
    int a_row = (lb & 1) * 8 + lr;
    int a_k   = (lb >> 1) * 8;
    int b_n   = (lb >> 1) * 8 + lr;
    int b_k   = (lb & 1) * 8;

    unsigned aH[2], aL[2], bH[2], bL[2];
#pragma unroll
    for (int mt = 0; mt < 2; mt++) {
        int row = rw + mt * 16 + a_row;
        aH[mt] = (unsigned)__cvta_generic_to_shared(sUh + row * SW + a_k);
        aL[mt] = (unsigned)__cvta_generic_to_shared(sUl + row * SW + a_k);
    }
#pragma unroll
    for (int jp = 0; jp < 2; jp++) {
        int n = nw + jp * 16 + b_n;
        bH[jp] = (unsigned)__cvta_generic_to_shared(sWh + n * SW + b_k);
        bL[jp] = (unsigned)__cvta_generic_to_shared(sWl + n * SW + b_k);
    }

#pragma unroll
    for (int ks = 0; ks < 8; ks++) {
        unsigned ko = (unsigned)ks * 32;      // 16 bf16 = 32 bytes
        unsigned Ah[2][4], Al[2][4];
        LDMX4(Ah[0], aH[0] + ko); LDMX4(Ah[1], aH[1] + ko);
        LDMX4(Al[0], aL[0] + ko); LDMX4(Al[1], aL[1] + ko);
#pragma unroll
        for (int jp = 0; jp < 2; jp++) {
            unsigned Bh[4], Bl[4];
            LDMX4(Bh, bH[jp] + ko);
            LDMX4(Bl, bL[jp] + ko);
#pragma unroll
            for (int mt = 0; mt < 2; mt++) {
#pragma unroll
                for (int jj = 0; jj < 2; jj++) {
                    int j = jp * 2 + jj;
                    MMA_BF16(acc[mt][j], Ah[mt][0], Ah[mt][1], Ah[mt][2], Ah[mt][3],
                             Bh[jj * 2], Bh[jj * 2 + 1]);
                    MMA_BF16(acc[mt][j], Al[mt][0], Al[mt][1], Al[mt][2], Al[mt][3],
                             Bh[jj * 2], Bh[jj * 2 + 1]);
                    MMA_BF16(acc[mt][j], Ah[mt][0], Ah[mt][1], Ah[mt][2], Ah[mt][3],
                             Bl[jj * 2], Bl[jj * 2 + 1]);
                }
            }
        }
    }

    // ---- epilogue: bias + relu; store fp32 in place + packed bf16 copy ----
    int g2 = lane >> 2, tg = lane & 3;
#pragma unroll
    for (int mt = 0; mt < 2; mt++) {
        int rA = rowBase + rw + mt * 16 + g2;
        int rB = rA + 8;
#pragma unroll
        for (int j = 0; j < 4; j++) {
            int c = nw + j * 8 + 2 * tg;
            float b0 = sB[c], b1 = sB[c + 1];
            float2 oA, oB;
            oA.x = fmaxf(acc[mt][j][0] + b0, 0.f);
            oA.y = fmaxf(acc[mt][j][1] + b1, 0.f);
            oB.x = fmaxf(acc[mt][j][2] + b0, 0.f);
            oB.y = fmaxf(acc[mt][j][3] + b1, 0.f);
            *(float2*)(u + (size_t)rA * HH + c) = oA;
            *(float2*)(u + (size_t)rB * HH + c) = oB;
            if (writeBF) {
                __nv_bfloat162 pA = __float22bfloat162_rn(oA);
                __nv_bfloat162 pB = __float22bfloat162_rn(oB);
                g_bufH[rA * 64 + (c >> 1)] = *(unsigned*)&pA;
                g_bufH[rB * 64 + (c >> 1)] = *(unsigned*)&pB;
            }
        }
    }
}

// ---------------------------------------------------------------- readout stage 1: partial node sums
__global__ void __launch_bounds__(128) k_sum(int bufsel) {
    const float* h = (bufsel == 1) ? g_bufA : g_bufB;
    int g = blockIdx.x >> 3, p = blockIdx.x & 7;
    int t = threadIdx.x;
    const float* base = h + (size_t)g * NN * HH + p * 64 * HH + t;
    float s0 = 0.f, s1 = 0.f;
#pragma unroll 8
    for (int r = 0; r < 64; r += 2) {
        s0 += base[r * HH];
        s1 += base[(r + 1) * HH];
    }
    g_part[(g * 8 + p) * HH + t] = s0 + s1;
}

// ---------------------------------------------------------------- readout stage 2: FCs + softmax
__global__ void __launch_bounds__(128) k_fc(const float* __restrict__ fc1w,
                                            const float* __restrict__ fc1b,
                                            const float* __restrict__ fc2w,
                                            const float* __restrict__ fc2b,
                                            float* __restrict__ out) {
    __shared__ float hg[HH];
    __shared__ float a1[HH];
    __shared__ float z[CC];
    __shared__ float ez[CC];

    int g = blockIdx.x;
    int t = threadIdx.x;

    float s = 0.f;
#pragma unroll
    for (int p = 0; p < 8; p++) s += g_part[(g * 8 + p) * HH + t];
    hg[t] = s;
    __syncthreads();

    {
        float acc = fc1b[t];
        for (int k = 0; k < HH; k++) acc += hg[k] * __ldg(&fc1w[k * HH + t]);
        a1[t] = fmaxf(acc, 0.f);
    }
    __syncthreads();

    if (t < CC) {
        float acc = fc2b[t];
        for (int k = 0; k < HH; k++) acc += a1[k] * __ldg(&fc2w[k * CC + t]);
        z[t] = acc;
    }
    __syncthreads();

    if (t < CC) {
        float m = z[0];
#pragma unroll
        for (int j = 1; j < CC; j++) m = fmaxf(m, z[j]);
        ez[t] = expf(z[t] - m);
    }
    __syncthreads();

    if (t < CC) {
        float ssum = 0.f;
#pragma unroll
        for (int j = 0; j < CC; j++) ssum += ez[j];
        out[g * CC + t] = ez[t] / ssum;
    }
}

// ---------------------------------------------------------------- launch
extern "C" void kernel_launch(void* const* d_in, const int* in_sizes, int n_in,
                              void* d_out, int out_size) {
    const float* x    = (const float*)d_in[0];
    const float* eps  = (const float*)d_in[1];
    const float* W    = (const float*)d_in[2];
    const float* b    = (const float*)d_in[3];
    const float* fc1w = (const float*)d_in[4];
    const float* fc1b = (const float*)d_in[5];
    const float* fc2w = (const float*)d_in[6];
    const float* fc2b = (const float*)d_in[7];
    const int*   src  = (const int*)d_in[8];
    const int*   dst  = (const int*)d_in[9];
    float* out = (float*)d_out;

    cudaFuncSetAttribute(k_gemm_tc, cudaFuncAttributeMaxDynamicSharedMemorySize,
                         SMEM_GEMM);

    k_csr<<<GG, 512>>>(src, dst);
    k_prepw<<<(LL * HH * 64 + 255) / 256, 256>>>(W);

    // 0: x->A, 1: A->B, 2: B->A, 3: A->B, 4: B->A. Final h in A.
    const int ssel[LL] = {0, 1, 2, 1, 2};
    const int dsel[LL] = {1, 2, 1, 2, 1};

    k_spmm<<<NV / 8, 256>>>(x, eps);
    k_gemm_tc<<<NV / 128, 512, SMEM_GEMM>>>(b, 0, dsel[0], 1);
    for (int l = 1; l < LL; l++) {
        k_spmm_bf<<<NV / 8, 256>>>(eps, l, ssel[l], dsel[l]);
        k_gemm_tc<<<NV / 128, 512, SMEM_GEMM>>>(b, l, dsel[l], (l < LL - 1) ? 1 : 0);
    }

    k_sum<<<GG * 8, 128>>>(1);
    k_fc<<<GG, 128>>>(fc1w, fc1b, fc2w, fc2b, out);
}